// round 5
// baseline (speedup 1.0000x reference)
#include <cuda_runtime.h>

#define NUM_CLASSES 23
#define HW (512*512)               // 262144 = 2^18
#define HW_SHIFT 18
#define NPIX (8*HW)                // 2097152
#define NPAIR (NPIX/2)             // 1048576
#define GRID 296
#define BLOCK 256
#define NWARPS (BLOCK/32)
#define NVALS (2*NUM_CLASSES + 1)  // 47
#define SMOOTH 1e-5f
#define LOG2E 1.4426950408889634f
#define LN2   0.6931471805599453f

__device__ float g_scratch[NVALS * GRID];
__device__ unsigned int g_count;   // zero-init; self-resetting each launch

__device__ __forceinline__ float warp_sum(float v) {
    #pragma unroll
    for (int off = 16; off; off >>= 1)
        v += __shfl_down_sync(0xffffffffu, v, off);
    return v;
}

// Raw MUFU ops (fast regardless of --use_fast_math); used OUTSIDE the hot
// dependency chains only where cheap.
__device__ __forceinline__ float fex2(float x) {
    float y; asm("ex2.approx.f32 %0, %1;" : "=f"(y) : "f"(x)); return y;
}
__device__ __forceinline__ float flg2(float x) {
    float y; asm("lg2.approx.f32 %0, %1;" : "=f"(y) : "f"(x)); return y;
}
__device__ __forceinline__ float frcp(float x) {
    float y; asm("rcp.approx.f32 %0, %1;" : "=f"(y) : "f"(x)); return y;
}

__global__ __launch_bounds__(BLOCK, 2)
void combined_loss_fused(const float* __restrict__ pred,
                         const int*  __restrict__ tgt,
                         float* __restrict__ out)
{
    float acc_int[NUM_CLASSES];
    float acc_den[NUM_CLASSES];
    #pragma unroll
    for (int c = 0; c < NUM_CLASSES; c++) { acc_int[c] = 0.f; acc_den[c] = 0.f; }
    float acc_ce_l2 = 0.f;                          // sum of log2-domain CE
    unsigned long long cntlo = 0ull, cnthi = 0ull;  // 5-bit packed class counts

    const int tid0   = blockIdx.x * BLOCK + threadIdx.x;
    const int stride = GRID * BLOCK;

    for (int q = tid0; q < NPAIR; q += stride) {
        const int p  = q << 1;
        const int b  = p >> HW_SHIFT;
        const int hw = p & (HW - 1);
        const float* base = pred + (size_t)b * (NUM_CLASSES * HW) + hw;
        const int2 t2 = ((const int2*)tgt)[q];
        const int t0 = t2.x, t1 = t2.y;

        // Single pass: load, exp (no max-subtract: logits O(1), fp32-safe),
        // running sums, and x_t select — all independent per class, full ILP.
        float ex0[NUM_CLASSES], ex1[NUM_CLASSES];
        float s0 = 0.f, s1 = 0.f;
        float xt0 = 0.f, xt1 = 0.f;
        #pragma unroll
        for (int c = 0; c < NUM_CLASSES; c++) {
            const float2 v = *(const float2*)(base + c * HW);
            xt0 = (c == t0) ? v.x : xt0;
            xt1 = (c == t1) ? v.y : xt1;
            const float e0 = fex2(v.x * LOG2E);
            const float e1 = fex2(v.y * LOG2E);
            ex0[c] = e0; ex1[c] = e1;
            s0 += e0; s1 += e1;
        }
        const float inv0 = frcp(s0);
        const float inv1 = frcp(s1);

        // CE in log2 domain: ln(s) - x_t = ln2 * (lg2(s) - x_t*log2e)
        acc_ce_l2 += (flg2(s0) - xt0 * LOG2E) + (flg2(s1) - xt1 * LOG2E);

        // Dice stats: predicated scatter, no select intermediates
        #pragma unroll
        for (int c = 0; c < NUM_CLASSES; c++) {
            const float pr0 = ex0[c] * inv0;
            const float pr1 = ex1[c] * inv1;
            acc_den[c] += pr0 + pr1;
            if (c == t0) acc_int[c] += pr0;
            if (c == t1) acc_int[c] += pr1;
        }

        // Packed per-class counts (5-bit fields; <=28 pixels/thread < 31)
        const bool hi0 = (t0 >= 12), hi1 = (t1 >= 12);
        const unsigned long long i0 = 1ull << (5 * (hi0 ? t0 - 12 : t0));
        const unsigned long long i1 = 1ull << (5 * (hi1 ? t1 - 12 : t1));
        if (hi0) cnthi += i0; else cntlo += i0;
        if (hi1) cnthi += i1; else cntlo += i1;
    }

    // Fold counts into the denominator (sum_p + count)
    #pragma unroll
    for (int c = 0; c < 12; c++)
        acc_den[c] += (float)((cntlo >> (5 * c)) & 31ull);
    #pragma unroll
    for (int c = 12; c < NUM_CLASSES; c++)
        acc_den[c] += (float)((cnthi >> (5 * (c - 12))) & 31ull);

    // Deterministic block reduction: warp shfl -> shared -> fixed-order sum
    __shared__ float s_part[NVALS][NWARPS];
    const int lane = threadIdx.x & 31;
    const int warp = threadIdx.x >> 5;

    #pragma unroll
    for (int c = 0; c < NUM_CLASSES; c++) {
        float v = warp_sum(acc_int[c]);
        if (lane == 0) s_part[c][warp] = v;
    }
    #pragma unroll
    for (int c = 0; c < NUM_CLASSES; c++) {
        float v = warp_sum(acc_den[c]);
        if (lane == 0) s_part[NUM_CLASSES + c][warp] = v;
    }
    {
        float v = warp_sum(acc_ce_l2);
        if (lane == 0) s_part[2 * NUM_CLASSES][warp] = v;
    }
    __syncthreads();

    if (threadIdx.x < NVALS) {
        float v = 0.f;
        #pragma unroll
        for (int w = 0; w < NWARPS; w++) v += s_part[threadIdx.x][w];
        g_scratch[threadIdx.x * GRID + blockIdx.x] = v;
    }

    // Last-block final reduction (fixed block-index order -> deterministic)
    __shared__ bool is_last;
    __threadfence();
    if (threadIdx.x == 0) {
        unsigned int v = atomicAdd(&g_count, 1u);
        is_last = (v == GRID - 1);
        if (is_last) g_count = 0u;   // reset for next graph replay
    }
    __syncthreads();
    if (!is_last) return;

    __shared__ float finals[NVALS];
    for (int v = warp; v < NVALS; v += NWARPS) {
        float s = 0.f;
        for (int bk = lane; bk < GRID; bk += 32)
            s += __ldcg(&g_scratch[v * GRID + bk]);
        s = warp_sum(s);
        if (lane == 0) finals[v] = s;
    }
    __syncthreads();

    if (threadIdx.x == 0) {
        float dl = 0.f;
        #pragma unroll
        for (int c = 0; c < NUM_CLASSES; c++) {
            const float inter = finals[c];
            const float den   = finals[NUM_CLASSES + c];
            dl += 1.0f - (2.0f * inter + SMOOTH) / (den + SMOOTH);
        }
        dl *= (1.0f / NUM_CLASSES);
        const float ce = finals[2 * NUM_CLASSES] * LN2 * (1.0f / (float)NPIX);
        out[0] = 0.5f * dl + 0.5f * ce;
    }
}

extern "C" void kernel_launch(void* const* d_in, const int* in_sizes, int n_in,
                              void* d_out, int out_size)
{
    const float* pred = (const float*)d_in[0];
    const int*   tgt  = (const int*)d_in[1];
    float*       out  = (float*)d_out;
    (void)in_sizes; (void)n_in; (void)out_size;

    combined_loss_fused<<<GRID, BLOCK>>>(pred, tgt, out);
}

// round 6
// speedup vs baseline: 1.1128x; 1.1128x over previous
#include <cuda_runtime.h>

#define NUM_CLASSES 23
#define HW (512*512)               // 262144 = 2^18
#define HW_SHIFT 18
#define NPIX (8*HW)                // 2097152
#define NPAIR (NPIX/2)             // 1048576
#define GRID 296
#define BLOCK 256
#define NWARPS (BLOCK/32)
#define NVALS (2*NUM_CLASSES + 1)  // 47
#define SMOOTH 1e-5f

__device__ float g_scratch[NVALS * GRID];
__device__ unsigned int g_count;   // zero-init; self-resetting each launch

__device__ __forceinline__ float warp_sum(float v) {
    #pragma unroll
    for (int off = 16; off; off >>= 1)
        v += __shfl_down_sync(0xffffffffu, v, off);
    return v;
}

__global__ __launch_bounds__(BLOCK, 2)
void combined_loss_fused(const float* __restrict__ pred,
                         const int*  __restrict__ tgt,
                         float* __restrict__ out)
{
    float acc_int[NUM_CLASSES];
    float acc_den[NUM_CLASSES];
    #pragma unroll
    for (int c = 0; c < NUM_CLASSES; c++) { acc_int[c] = 0.f; acc_den[c] = 0.f; }
    float acc_ce = 0.f;

    const int tid0   = blockIdx.x * BLOCK + threadIdx.x;
    const int stride = GRID * BLOCK;

    for (int q = tid0; q < NPAIR; q += stride) {
        const int p  = q << 1;
        const int b  = p >> HW_SHIFT;
        const int hw = p & (HW - 1);
        const float* base = pred + (size_t)b * (NUM_CLASSES * HW) + hw;
        const int2 t2 = ((const int2*)tgt)[q];

        // Pass A: loads only feed x[] + cheap selects -> ptxas hoists all 23
        // LDG.64 (46 live regs), MLP ~23. No max-subtract: logits are O(1),
        // exp is fp32-safe (validated rel_err 0.0).
        float2 x[NUM_CLASSES];
        float xt0 = 0.f, xt1 = 0.f;
        #pragma unroll
        for (int c = 0; c < NUM_CLASSES; c++) {
            x[c] = *(const float2*)(base + c * HW);
            xt0 = (c == t2.x) ? x[c].x : xt0;
            xt1 = (c == t2.y) ? x[c].y : xt1;
        }

        // Pass B: exp in place (register reuse keeps live set at 46) + sum
        float s0 = 0.f, s1 = 0.f;
        #pragma unroll
        for (int c = 0; c < NUM_CLASSES; c++) {
            x[c].x = __expf(x[c].x);
            x[c].y = __expf(x[c].y);
            s0 += x[c].x;
            s1 += x[c].y;
        }
        const float inv0 = 1.0f / s0;
        const float inv1 = 1.0f / s1;

        // Pass C: per-class dice stats (select-based, proven scheduling)
        #pragma unroll
        for (int c = 0; c < NUM_CLASSES; c++) {
            const float pr0 = x[c].x * inv0;
            const float pr1 = x[c].y * inv1;
            const bool h0 = (c == t2.x);
            const bool h1 = (c == t2.y);
            acc_den[c] += (h0 ? (pr0 + 1.0f) : pr0) + (h1 ? (pr1 + 1.0f) : pr1);
            acc_int[c] += (h0 ? pr0 : 0.0f) + (h1 ? pr1 : 0.0f);
        }

        // CE: -(logp_t) = log(sumexp) - x_t   (no max term)
        acc_ce += (__logf(s0) - xt0) + (__logf(s1) - xt1);
    }

    // Deterministic block reduction: warp shfl -> shared -> fixed-order sum
    __shared__ float s_part[NVALS][NWARPS];
    const int lane = threadIdx.x & 31;
    const int warp = threadIdx.x >> 5;

    #pragma unroll
    for (int c = 0; c < NUM_CLASSES; c++) {
        float v = warp_sum(acc_int[c]);
        if (lane == 0) s_part[c][warp] = v;
    }
    #pragma unroll
    for (int c = 0; c < NUM_CLASSES; c++) {
        float v = warp_sum(acc_den[c]);
        if (lane == 0) s_part[NUM_CLASSES + c][warp] = v;
    }
    {
        float v = warp_sum(acc_ce);
        if (lane == 0) s_part[2 * NUM_CLASSES][warp] = v;
    }
    __syncthreads();

    if (threadIdx.x < NVALS) {
        float v = 0.f;
        #pragma unroll
        for (int w = 0; w < NWARPS; w++) v += s_part[threadIdx.x][w];
        g_scratch[threadIdx.x * GRID + blockIdx.x] = v;
    }

    // Last-block final reduction (fixed block-index order -> deterministic)
    __shared__ bool is_last;
    __threadfence();
    if (threadIdx.x == 0) {
        unsigned int v = atomicAdd(&g_count, 1u);
        is_last = (v == GRID - 1);
        if (is_last) g_count = 0u;   // reset for next graph replay
    }
    __syncthreads();
    if (!is_last) return;

    __shared__ float finals[NVALS];
    for (int v = warp; v < NVALS; v += NWARPS) {
        float s = 0.f;
        for (int bk = lane; bk < GRID; bk += 32)
            s += __ldcg(&g_scratch[v * GRID + bk]);
        s = warp_sum(s);
        if (lane == 0) finals[v] = s;
    }
    __syncthreads();

    if (threadIdx.x == 0) {
        float dl = 0.f;
        #pragma unroll
        for (int c = 0; c < NUM_CLASSES; c++) {
            const float inter = finals[c];
            const float den   = finals[NUM_CLASSES + c];
            dl += 1.0f - (2.0f * inter + SMOOTH) / (den + SMOOTH);
        }
        dl *= (1.0f / NUM_CLASSES);
        const float ce = finals[2 * NUM_CLASSES] * (1.0f / (float)NPIX);
        out[0] = 0.5f * dl + 0.5f * ce;
    }
}

extern "C" void kernel_launch(void* const* d_in, const int* in_sizes, int n_in,
                              void* d_out, int out_size)
{
    const float* pred = (const float*)d_in[0];
    const int*   tgt  = (const int*)d_in[1];
    float*       out  = (float*)d_out;
    (void)in_sizes; (void)n_in; (void)out_size;

    combined_loss_fused<<<GRID, BLOCK>>>(pred, tgt, out);
}

// round 7
// speedup vs baseline: 1.4565x; 1.3089x over previous
#include <cuda_runtime.h>

#define NUM_CLASSES 23
#define HW (512*512)               // 262144 = 2^18
#define HW_SHIFT 18
#define NPIX (8*HW)                // 2097152
#define NPAIR (NPIX/2)             // 1048576
#define GRID 296
#define BLOCK 256
#define NWARPS (BLOCK/32)
#define NVALS (2*NUM_CLASSES + 1)  // 47
#define SMOOTH 1e-5f
#define CNT_SHIFT 43
#define FIX_SCALE 16777216.0f      // 2^24
#define INV_FIX   (1.0f/16777216.0f)

__device__ float g_scratch[NVALS * GRID];
__device__ unsigned int g_count;   // zero-init; self-resetting each launch

__device__ __forceinline__ float warp_sum(float v) {
    #pragma unroll
    for (int off = 16; off; off >>= 1)
        v += __shfl_down_sync(0xffffffffu, v, off);
    return v;
}

__global__ __launch_bounds__(BLOCK, 2)
void combined_loss_fused(const float* __restrict__ pred,
                         const int*  __restrict__ tgt,
                         float* __restrict__ out)
{
    // Per-warp packed accumulators: bits[43:64)=count, bits[0:43)=inter*2^24
    __shared__ unsigned long long s_ic[NWARPS][NUM_CLASSES];
    for (int i = threadIdx.x; i < NWARPS * NUM_CLASSES; i += BLOCK)
        ((unsigned long long*)s_ic)[i] = 0ull;
    __syncthreads();

    float acc_den[NUM_CLASSES];
    #pragma unroll
    for (int c = 0; c < NUM_CLASSES; c++) acc_den[c] = 0.f;
    float acc_ce = 0.f;

    const int lane = threadIdx.x & 31;
    const int warp = threadIdx.x >> 5;
    const int tid0   = blockIdx.x * BLOCK + threadIdx.x;
    const int stride = GRID * BLOCK;

    for (int q = tid0; q < NPAIR; q += stride) {
        const int p  = q << 1;
        const int b  = p >> HW_SHIFT;
        const int hw = p & (HW - 1);
        const float* base = pred + (size_t)b * (NUM_CLASSES * HW) + hw;
        const int2 t2 = ((const int2*)tgt)[q];

        // Pass A (R3-proven): batch loads; FMAX chain = scheduling barrier
        // forcing all 23 LDG.64 in flight before any exp (MLP~23).
        float2 x[NUM_CLASSES];
        float m0 = -1e30f, m1 = -1e30f;
        float xt0 = 0.f, xt1 = 0.f;
        #pragma unroll
        for (int c = 0; c < NUM_CLASSES; c++) {
            x[c] = *(const float2*)(base + c * HW);
            m0 = fmaxf(m0, x[c].x);
            m1 = fmaxf(m1, x[c].y);
            xt0 = (c == t2.x) ? x[c].x : xt0;
            xt1 = (c == t2.y) ? x[c].y : xt1;
        }

        // Pass B: exp in place + sums
        float s0 = 0.f, s1 = 0.f;
        #pragma unroll
        for (int c = 0; c < NUM_CLASSES; c++) {
            x[c].x = __expf(x[c].x - m0);
            x[c].y = __expf(x[c].y - m1);
            s0 += x[c].x;
            s1 += x[c].y;
        }
        const float inv0 = 1.0f / s0;
        const float inv1 = 1.0f / s1;

        // Pass C: denominator only (3 ops/class); counts/inter via atomics
        #pragma unroll
        for (int c = 0; c < NUM_CLASSES; c++)
            acc_den[c] += fmaf(x[c].y, inv1, x[c].x * inv0);

        // CE + p_t (from xt, no per-class selects)
        acc_ce += ((m0 + __logf(s0)) - xt0) + ((m1 + __logf(s1)) - xt1);
        const float pt0 = __expf(xt0 - m0) * inv0;
        const float pt1 = __expf(xt1 - m1) * inv1;

        const unsigned long long u0 =
            (unsigned long long)(pt0 * FIX_SCALE) + (1ull << CNT_SHIFT);
        const unsigned long long u1 =
            (unsigned long long)(pt1 * FIX_SCALE) + (1ull << CNT_SHIFT);
        atomicAdd(&s_ic[warp][t2.x], u0);
        atomicAdd(&s_ic[warp][t2.y], u1);
    }

    // Deterministic block reduction for den + ce
    __shared__ float s_part[NUM_CLASSES + 1][NWARPS];
    #pragma unroll
    for (int c = 0; c < NUM_CLASSES; c++) {
        float v = warp_sum(acc_den[c]);
        if (lane == 0) s_part[c][warp] = v;
    }
    {
        float v = warp_sum(acc_ce);
        if (lane == 0) s_part[NUM_CLASSES][warp] = v;
    }
    __syncthreads();

    if (threadIdx.x < NUM_CLASSES) {
        const int c = threadIdx.x;
        unsigned long long tot = 0ull;
        float den = 0.f;
        #pragma unroll
        for (int w = 0; w < NWARPS; w++) {
            tot += s_ic[w][c];
            den += s_part[c][w];
        }
        const float inter = (float)(tot & ((1ull << CNT_SHIFT) - 1ull)) * INV_FIX;
        const float cnt   = (float)(tot >> CNT_SHIFT);
        g_scratch[c * GRID + blockIdx.x] = inter;
        g_scratch[(NUM_CLASSES + c) * GRID + blockIdx.x] = den + cnt;
    } else if (threadIdx.x == NUM_CLASSES) {
        float ce = 0.f;
        #pragma unroll
        for (int w = 0; w < NWARPS; w++) ce += s_part[NUM_CLASSES][w];
        g_scratch[2 * NUM_CLASSES * GRID + blockIdx.x] = ce;
    }

    // Last-block final reduction (fixed block-index order -> deterministic)
    __shared__ bool is_last;
    __threadfence();
    if (threadIdx.x == 0) {
        unsigned int v = atomicAdd(&g_count, 1u);
        is_last = (v == GRID - 1);
        if (is_last) g_count = 0u;   // reset for next graph replay
    }
    __syncthreads();
    if (!is_last) return;

    __shared__ float finals[NVALS];
    for (int v = warp; v < NVALS; v += NWARPS) {
        float s = 0.f;
        for (int bk = lane; bk < GRID; bk += 32)
            s += __ldcg(&g_scratch[v * GRID + bk]);
        s = warp_sum(s);
        if (lane == 0) finals[v] = s;
    }
    __syncthreads();

    if (threadIdx.x == 0) {
        float dl = 0.f;
        #pragma unroll
        for (int c = 0; c < NUM_CLASSES; c++) {
            const float inter = finals[c];
            const float den   = finals[NUM_CLASSES + c];
            dl += 1.0f - (2.0f * inter + SMOOTH) / (den + SMOOTH);
        }
        dl *= (1.0f / NUM_CLASSES);
        const float ce = finals[2 * NUM_CLASSES] * (1.0f / (float)NPIX);
        out[0] = 0.5f * dl + 0.5f * ce;
    }
}

extern "C" void kernel_launch(void* const* d_in, const int* in_sizes, int n_in,
                              void* d_out, int out_size)
{
    const float* pred = (const float*)d_in[0];
    const int*   tgt  = (const int*)d_in[1];
    float*       out  = (float*)d_out;
    (void)in_sizes; (void)n_in; (void)out_size;

    combined_loss_fused<<<GRID, BLOCK>>>(pred, tgt, out);
}